// round 1
// baseline (speedup 1.0000x reference)
#include <cuda_runtime.h>
#include <math.h>

#define N_CELLS 10000
#define P_GENES 8000
#define L_FAC   100
#define LAM_F   0.01
#define DELTA_F 0.001f

// ---------------- device scratch (module-static, no allocation) ----------------
__device__ float g_th [P_GENES * L_FAC];   // softmax(theta) rows
__device__ float g_thp[P_GENES * L_FAC];   // theta_ = th * (sigmoid(gs)+delta)
__device__ float g_B  [P_GENES * L_FAC];   // B = th @ et
__device__ float g_a  [N_CELLS * L_FAC];   // exp(alpha)
__device__ float g_et [L_FAC * L_FAC];     // symmetrized sigmoid(eta)
__device__ double g_acc[2];                // [0]=s1 (recon part), [1]=s23 (mat part)

__device__ __forceinline__ float sigmoidf_(float x) {
    return 1.0f / (1.0f + expf(-x));
}

// ---------------- init ----------------
__global__ void init_kernel() {
    g_acc[0] = 0.0;
    g_acc[1] = 0.0;
}

// ---------------- et = 0.5*(sigmoid(eta)+sigmoid(eta)^T) ----------------
__global__ void et_kernel(const float* __restrict__ eta) {
    int idx = blockIdx.x * blockDim.x + threadIdx.x;
    if (idx >= L_FAC * L_FAC) return;
    int i = idx / L_FAC, j = idx % L_FAC;
    g_et[idx] = 0.5f * (sigmoidf_(eta[i * L_FAC + j]) + sigmoidf_(eta[j * L_FAC + i]));
}

// ---------------- a = exp(alpha) ----------------
__global__ void expa_kernel(const float* __restrict__ alpha) {
    int idx = blockIdx.x * blockDim.x + threadIdx.x;
    if (idx < N_CELLS * L_FAC) g_a[idx] = expf(alpha[idx]);
}

// ---------------- per-gene: softmax row, theta_, B = th @ et ----------------
__global__ void theta_kernel(const float* __restrict__ theta,
                             const float* __restrict__ gs) {
    int j = blockIdx.x;          // gene row
    int t = threadIdx.x;         // 128 threads
    __shared__ float sv[128];
    __shared__ float s_th[L_FAC];

    float v = (t < L_FAC) ? theta[j * L_FAC + t] : -1e30f;
    sv[t] = v; __syncthreads();
    for (int s = 64; s > 0; s >>= 1) {
        if (t < s) sv[t] = fmaxf(sv[t], sv[t + s]);
        __syncthreads();
    }
    float mx = sv[0]; __syncthreads();

    float e = (t < L_FAC) ? expf(v - mx) : 0.0f;
    sv[t] = e; __syncthreads();
    for (int s = 64; s > 0; s >>= 1) {
        if (t < s) sv[t] += sv[t + s];
        __syncthreads();
    }
    float inv = 1.0f / sv[0];

    float th = e * inv;
    if (t < L_FAC) {
        s_th[t] = th;
        g_th[j * L_FAC + t] = th;
        float g = sigmoidf_(gs[j]);
        g_thp[j * L_FAC + t] = th * (g + DELTA_F);
    }
    __syncthreads();

    if (t < L_FAC) {
        float acc = 0.0f;
        #pragma unroll 4
        for (int m = 0; m < L_FAC; m++)
            acc += s_th[m] * g_et[m * L_FAC + t];
        g_B[j * L_FAC + t] = acc;
    }
}

// =====================================================================
// Fused GEMM + epilogue kernels.
// Tile: 64x64 per block, 256 threads, 4x4 outputs per thread, K staged
// in two 50-wide smem chunks (K=100). Both operands are K-major rows.
// =====================================================================
#define BM 64
#define BN 64
#define BK 50

// ---- recon: s1 += sum over tile of (X*log(recon) - recon) ----
__global__ void __launch_bounds__(256)
recon_kernel(const float* __restrict__ X) {
    __shared__ float As[BK][BM + 1];
    __shared__ float Bs[BK][BN + 1];
    __shared__ float red[256];

    int tid = threadIdx.x;
    int tx = tid & 15;          // col group
    int ty = tid >> 4;          // row group
    int rowBase = blockIdx.y * BM;   // N dim (cells)
    int colBase = blockIdx.x * BN;   // P dim (genes)

    float acc[4][4];
    #pragma unroll
    for (int i = 0; i < 4; i++)
        #pragma unroll
        for (int j = 0; j < 4; j++) acc[i][j] = 0.0f;

    for (int k0 = 0; k0 < L_FAC; k0 += BK) {
        // stage A tile (exp(alpha))
        for (int i = tid; i < BM * BK; i += 256) {
            int kk = i % BK, m = i / BK;
            int gr = rowBase + m;
            As[kk][m] = (gr < N_CELLS) ? g_a[gr * L_FAC + k0 + kk] : 0.0f;
        }
        // stage B tile (theta_)
        for (int i = tid; i < BN * BK; i += 256) {
            int kk = i % BK, n = i / BK;
            int gc = colBase + n;
            Bs[kk][n] = g_thp[gc * L_FAC + k0 + kk];
        }
        __syncthreads();

        #pragma unroll 10
        for (int kk = 0; kk < BK; kk++) {
            float av[4], bv[4];
            #pragma unroll
            for (int i = 0; i < 4; i++) av[i] = As[kk][ty * 4 + i];
            #pragma unroll
            for (int j = 0; j < 4; j++) bv[j] = Bs[kk][tx * 4 + j];
            #pragma unroll
            for (int i = 0; i < 4; i++)
                #pragma unroll
                for (int j = 0; j < 4; j++)
                    acc[i][j] = fmaf(av[i], bv[j], acc[i][j]);
        }
        __syncthreads();
    }

    // epilogue: X*log(recon) - recon
    float lsum = 0.0f;
    #pragma unroll
    for (int i = 0; i < 4; i++) {
        int r = rowBase + ty * 4 + i;
        if (r < N_CELLS) {
            const float4 x4 = *reinterpret_cast<const float4*>(
                &X[(size_t)r * P_GENES + colBase + tx * 4]);
            float xs[4] = {x4.x, x4.y, x4.z, x4.w};
            #pragma unroll
            for (int j = 0; j < 4; j++) {
                float rec = acc[i][j];
                float t = (xs[j] > 0.0f) ? xs[j] * __logf(rec) : 0.0f;
                lsum += t - rec;
            }
        }
    }

    red[tid] = lsum; __syncthreads();
    for (int s = 128; s > 0; s >>= 1) {
        if (tid < s) red[tid] += red[tid + s];
        __syncthreads();
    }
    if (tid == 0) atomicAdd(&g_acc[0], (double)red[0]);
}

// ---- mat: s23 += sum over tile of log(arg2 or arg3), off-diagonal ----
__global__ void __launch_bounds__(256)
mat_kernel(const float* __restrict__ adj,
           const float* __restrict__ kappa,
           const float* __restrict__ rho) {
    __shared__ float As[BK][BM + 1];
    __shared__ float Bs[BK][BN + 1];
    __shared__ float red[256];

    int tid = threadIdx.x;
    int tx = tid & 15;
    int ty = tid >> 4;
    int rowBase = blockIdx.y * BM;   // P dim (rows of B = th@et)
    int colBase = blockIdx.x * BN;   // P dim (rows of th)

    float acc[4][4];
    #pragma unroll
    for (int i = 0; i < 4; i++)
        #pragma unroll
        for (int j = 0; j < 4; j++) acc[i][j] = 0.0f;

    for (int k0 = 0; k0 < L_FAC; k0 += BK) {
        for (int i = tid; i < BM * BK; i += 256) {
            int kk = i % BK, m = i / BK;
            As[kk][m] = g_B[(rowBase + m) * L_FAC + k0 + kk];
        }
        for (int i = tid; i < BN * BK; i += 256) {
            int kk = i % BK, n = i / BK;
            Bs[kk][n] = g_th[(colBase + n) * L_FAC + k0 + kk];
        }
        __syncthreads();

        #pragma unroll 10
        for (int kk = 0; kk < BK; kk++) {
            float av[4], bv[4];
            #pragma unroll
            for (int i = 0; i < 4; i++) av[i] = As[kk][ty * 4 + i];
            #pragma unroll
            for (int j = 0; j < 4; j++) bv[j] = Bs[kk][tx * 4 + j];
            #pragma unroll
            for (int i = 0; i < 4; i++)
                #pragma unroll
                for (int j = 0; j < 4; j++)
                    acc[i][j] = fmaf(av[i], bv[j], acc[i][j]);
        }
        __syncthreads();
    }

    // constants
    float sk = sigmoidf_(kappa[0]);
    float sr = sigmoidf_(rho[0]);
    float A  = (1.0f - sr) * (1.0f - sk);   // (1-r)(1-k)
    float C2 = (1.0f - sr) * sk;            // (1-r)k
    float C3 = A + sr;                      // A*(1-m)+r = C3 - A*m

    float lsum = 0.0f;
    #pragma unroll
    for (int i = 0; i < 4; i++) {
        int r = rowBase + ty * 4 + i;
        const float4 a4 = *reinterpret_cast<const float4*>(
            &adj[(size_t)r * P_GENES + colBase + tx * 4]);
        float av[4] = {a4.x, a4.y, a4.z, a4.w};
        #pragma unroll
        for (int j = 0; j < 4; j++) {
            int c = colBase + tx * 4 + j;
            float m = acc[i][j];
            float arg = (av[j] > 0.5f) ? fmaf(A, m, C2) : fmaf(-A, m, C3);
            if (r != c) lsum += __logf(arg);
        }
    }

    red[tid] = lsum; __syncthreads();
    for (int s = 128; s > 0; s >>= 1) {
        if (tid < s) red[tid] += red[tid + s];
        __syncthreads();
    }
    if (tid == 0) atomicAdd(&g_acc[1], (double)red[0]);
}

// ---------------- finalize ----------------
__global__ void fin_kernel(float* out) {
    out[0] = (float)(-(LAM_F * g_acc[0] + g_acc[1]));
}

// ---------------- launch ----------------
extern "C" void kernel_launch(void* const* d_in, const int* in_sizes, int n_in,
                              void* d_out, int out_size) {
    const float* X     = (const float*)d_in[0];
    const float* adj   = (const float*)d_in[1];
    // d_in[2] adj_1m, d_in[3] weights: derivable from adj (binary), unused
    const float* theta = (const float*)d_in[4];
    const float* alpha = (const float*)d_in[5];
    const float* eta   = (const float*)d_in[6];
    const float* gs    = (const float*)d_in[7];
    const float* kappa = (const float*)d_in[8];
    const float* rho   = (const float*)d_in[9];
    float* out = (float*)d_out;

    init_kernel<<<1, 1>>>();
    et_kernel<<<(L_FAC * L_FAC + 255) / 256, 256>>>(eta);
    expa_kernel<<<(N_CELLS * L_FAC + 255) / 256, 256>>>(alpha);
    theta_kernel<<<P_GENES, 128>>>(theta, gs);

    dim3 gRecon(P_GENES / BN, (N_CELLS + BM - 1) / BM);   // 125 x 157
    recon_kernel<<<gRecon, 256>>>(X);

    dim3 gMat(P_GENES / BN, P_GENES / BM);                // 125 x 125
    mat_kernel<<<gMat, 256>>>(adj, kappa, rho);

    fin_kernel<<<1, 1>>>(out);
}

// round 2
// speedup vs baseline: 2.3025x; 2.3025x over previous
#include <cuda_runtime.h>
#include <cuda_bf16.h>
#include <math.h>

#define N_CELLS 10000
#define P_GENES 8000
#define L_FAC   100
#define KP      112      // padded K in global bf16 operand arrays
#define KS      120      // smem row stride in halves (bank-conflict-free)
#define LAM_D   0.01
#define DELTA_F 0.001f

#define GRID_X  63                    // ceil(8000/128)
#define GRID_Y1 79                    // ceil(10000/128)
#define NPART1  (GRID_X * GRID_Y1)    // 4977
#define NPART2  (GRID_X * GRID_X)     // 3969

// ---------------- device scratch ----------------
__device__ __align__(16) __nv_bfloat16 g_a_bf  [N_CELLS * KP];
__device__ __align__(16) __nv_bfloat16 g_thp_bf[P_GENES * KP];
__device__ __align__(16) __nv_bfloat16 g_th_bf [P_GENES * KP];
__device__ __align__(16) __nv_bfloat16 g_B_bf  [P_GENES * KP];
__device__ float  g_et[L_FAC * L_FAC];
__device__ double g_part1[5120];
__device__ double g_part2[4096];

__device__ __forceinline__ float sigmoidf_(float x) {
    return 1.0f / (1.0f + expf(-x));
}

// ---------------- et = 0.5*(sigmoid(eta)+sigmoid(eta)^T) ----------------
__global__ void et_kernel(const float* __restrict__ eta) {
    int idx = blockIdx.x * blockDim.x + threadIdx.x;
    if (idx >= L_FAC * L_FAC) return;
    int i = idx / L_FAC, j = idx % L_FAC;
    g_et[idx] = 0.5f * (sigmoidf_(eta[i * L_FAC + j]) + sigmoidf_(eta[j * L_FAC + i]));
}

// ---------------- a = exp(alpha), bf16, K-padded ----------------
__global__ void expa_kernel(const float* __restrict__ alpha) {
    int idx = blockIdx.x * blockDim.x + threadIdx.x;
    if (idx >= N_CELLS * KP) return;
    int row = idx / KP, k = idx % KP;
    float v = (k < L_FAC) ? expf(alpha[row * L_FAC + k]) : 0.0f;
    g_a_bf[idx] = __float2bfloat16(v);
}

// ---------------- per-gene: softmax, theta_, B = th@et ; 16 genes/block ----
__global__ void __launch_bounds__(256)
theta_kernel(const float* __restrict__ theta, const float* __restrict__ gs) {
    __shared__ float et_s[L_FAC * L_FAC];   // 40 KB
    __shared__ float th_s[16][L_FAC];       // 6.4 KB

    int tid = threadIdx.x;
    for (int i = tid; i < L_FAC * L_FAC; i += 256) et_s[i] = g_et[i];

    int warp = tid >> 5, lane = tid & 31;
    int rowl = warp * 2 + (lane >> 4);      // 0..15 local gene row
    int l16  = lane & 15;
    int gene = blockIdx.x * 16 + rowl;      // P divisible by 16

    // softmax over L=100 with 16 lanes per row
    float v[7];
    float mx = -1e30f;
    #pragma unroll
    for (int j = 0; j < 7; j++) {
        int idx = l16 + 16 * j;
        v[j] = (idx < L_FAC) ? theta[gene * L_FAC + idx] : -1e30f;
        mx = fmaxf(mx, v[j]);
    }
    #pragma unroll
    for (int off = 8; off > 0; off >>= 1)
        mx = fmaxf(mx, __shfl_xor_sync(0xffffffff, mx, off, 16));
    float sum = 0.0f;
    #pragma unroll
    for (int j = 0; j < 7; j++) {
        int idx = l16 + 16 * j;
        v[j] = (idx < L_FAC) ? expf(v[j] - mx) : 0.0f;
        sum += v[j];
    }
    #pragma unroll
    for (int off = 8; off > 0; off >>= 1)
        sum += __shfl_xor_sync(0xffffffff, sum, off, 16);
    float inv = 1.0f / sum;
    float gsc = sigmoidf_(gs[gene]) + DELTA_F;

    #pragma unroll
    for (int j = 0; j < 7; j++) {
        int idx = l16 + 16 * j;
        if (idx < L_FAC) {
            float th = v[j] * inv;
            th_s[rowl][idx] = th;
            g_th_bf [gene * KP + idx] = __float2bfloat16(th);
            g_thp_bf[gene * KP + idx] = __float2bfloat16(th * gsc);
        }
    }
    if (l16 < 12) {  // zero pads k=100..111
        g_th_bf [gene * KP + L_FAC + l16] = __float2bfloat16(0.0f);
        g_thp_bf[gene * KP + L_FAC + l16] = __float2bfloat16(0.0f);
        g_B_bf  [gene * KP + L_FAC + l16] = __float2bfloat16(0.0f);
    }
    __syncthreads();

    // B = th @ et  (16 x 100)
    for (int idx = tid; idx < 16 * L_FAC; idx += 256) {
        int r = idx / L_FAC, c = idx % L_FAC;
        float acc = 0.0f;
        #pragma unroll 4
        for (int m = 0; m < L_FAC; m++)
            acc = fmaf(th_s[r][m], et_s[m * L_FAC + c], acc);
        g_B_bf[(blockIdx.x * 16 + r) * KP + c] = __float2bfloat16(acc);
    }
}

// =====================================================================
// bf16 mma.sync GEMM: 128x128 block tile, 256 thr (8 warps 2x4),
// warp tile 64x32, whole K panel (112) staged once in smem.
// =====================================================================
__device__ __forceinline__ void mma16816(float c[4], const unsigned a[4], const unsigned b[2]) {
    asm volatile(
        "mma.sync.aligned.m16n8k16.row.col.f32.bf16.bf16.f32 "
        "{%0,%1,%2,%3}, {%4,%5,%6,%7}, {%8,%9}, {%0,%1,%2,%3};"
        : "+f"(c[0]), "+f"(c[1]), "+f"(c[2]), "+f"(c[3])
        : "r"(a[0]), "r"(a[1]), "r"(a[2]), "r"(a[3]), "r"(b[0]), "r"(b[1]));
}

__device__ __forceinline__ void gemm_main(
    const __nv_bfloat16* __restrict__ Aglob, int Arows, int rowBase,
    const __nv_bfloat16* __restrict__ Bglob, int Brows, int colBase,
    float acc[4][4][4], char* smem, int tid)
{
    __nv_bfloat16* As = (__nv_bfloat16*)smem;
    __nv_bfloat16* Bs = As + 128 * KS;

    for (int i = tid; i < 128 * 14; i += 256) {
        int r = i / 14, c = i % 14;
        int gr = rowBase + r;
        uint4 val = make_uint4(0u, 0u, 0u, 0u);
        if (gr < Arows) val = *(const uint4*)(Aglob + (size_t)gr * KP + c * 8);
        *(uint4*)((char*)As + r * (KS * 2) + c * 16) = val;
    }
    for (int i = tid; i < 128 * 14; i += 256) {
        int r = i / 14, c = i % 14;
        int gr = colBase + r;
        uint4 val = make_uint4(0u, 0u, 0u, 0u);
        if (gr < Brows) val = *(const uint4*)(Bglob + (size_t)gr * KP + c * 8);
        *(uint4*)((char*)Bs + r * (KS * 2) + c * 16) = val;
    }
    __syncthreads();

    int lane = tid & 31, warp = tid >> 5;
    int wm = warp >> 2, wn = warp & 3;
    int rq = lane >> 2;            // 0..7
    int kp = (lane & 3) << 1;      // 0,2,4,6

    #pragma unroll
    for (int mi = 0; mi < 4; mi++)
        #pragma unroll
        for (int nj = 0; nj < 4; nj++)
            #pragma unroll
            for (int q = 0; q < 4; q++) acc[mi][nj][q] = 0.0f;

    #pragma unroll
    for (int ks = 0; ks < 7; ks++) {
        int k0 = ks * 16 + kp;
        unsigned aF[4][4], bF[4][2];
        #pragma unroll
        for (int mi = 0; mi < 4; mi++) {
            const __nv_bfloat16* p = As + (wm * 64 + mi * 16 + rq) * KS + k0;
            aF[mi][0] = *(const unsigned*)(p);
            aF[mi][1] = *(const unsigned*)(p + 8 * KS);
            aF[mi][2] = *(const unsigned*)(p + 8);
            aF[mi][3] = *(const unsigned*)(p + 8 * KS + 8);
        }
        #pragma unroll
        for (int nj = 0; nj < 4; nj++) {
            const __nv_bfloat16* p = Bs + (wn * 32 + nj * 8 + rq) * KS + k0;
            bF[nj][0] = *(const unsigned*)(p);
            bF[nj][1] = *(const unsigned*)(p + 8);
        }
        #pragma unroll
        for (int mi = 0; mi < 4; mi++)
            #pragma unroll
            for (int nj = 0; nj < 4; nj++)
                mma16816(acc[mi][nj], aF[mi], bF[nj]);
    }
}

__device__ __forceinline__ double block_reduce(float lsum, int tid) {
    __shared__ float red[8];
    #pragma unroll
    for (int off = 16; off > 0; off >>= 1)
        lsum += __shfl_xor_sync(0xffffffff, lsum, off);
    if ((tid & 31) == 0) red[tid >> 5] = lsum;
    __syncthreads();
    double t = 0.0;
    if (tid == 0) {
        #pragma unroll
        for (int w = 0; w < 8; w++) t += (double)red[w];
    }
    return t;
}

// ---- recon kernel: C = a @ thp^T, epilogue xlogy(X,C) - C ----
__global__ void __launch_bounds__(256)
recon_kernel(const float* __restrict__ X) {
    extern __shared__ char dsm[];
    int tid = threadIdx.x;
    int rowBase = blockIdx.y * 128;   // cells
    int colBase = blockIdx.x * 128;   // genes

    float acc[4][4][4];
    gemm_main(g_a_bf, N_CELLS, rowBase, g_thp_bf, P_GENES, colBase, acc, dsm, tid);

    int lane = tid & 31, warp = tid >> 5;
    int wm = warp >> 2, wn = warp & 3;
    int rq = lane >> 2, kp = (lane & 3) << 1;

    float lsum = 0.0f;
    #pragma unroll
    for (int mi = 0; mi < 4; mi++) {
        #pragma unroll
        for (int nj = 0; nj < 4; nj++) {
            int r = rowBase + wm * 64 + mi * 16 + rq;
            int c = colBase + wn * 32 + nj * 8 + kp;
            if (c < P_GENES) {
                if (r < N_CELLS) {
                    float2 x = *(const float2*)(X + (size_t)r * P_GENES + c);
                    float rec = acc[mi][nj][0];
                    lsum += ((x.x > 0.0f) ? x.x * __logf(rec) : 0.0f) - rec;
                    rec = acc[mi][nj][1];
                    lsum += ((x.y > 0.0f) ? x.y * __logf(rec) : 0.0f) - rec;
                }
                if (r + 8 < N_CELLS) {
                    float2 x = *(const float2*)(X + (size_t)(r + 8) * P_GENES + c);
                    float rec = acc[mi][nj][2];
                    lsum += ((x.x > 0.0f) ? x.x * __logf(rec) : 0.0f) - rec;
                    rec = acc[mi][nj][3];
                    lsum += ((x.y > 0.0f) ? x.y * __logf(rec) : 0.0f) - rec;
                }
            }
        }
    }
    double t = block_reduce(lsum, tid);
    if (tid == 0) g_part1[blockIdx.y * gridDim.x + blockIdx.x] = t;
}

// ---- mat kernel: M = B @ th^T, epilogue graph-prior logs ----
__global__ void __launch_bounds__(256)
mat_kernel(const float* __restrict__ adj,
           const float* __restrict__ kappa,
           const float* __restrict__ rho) {
    extern __shared__ char dsm[];
    int tid = threadIdx.x;
    int rowBase = blockIdx.y * 128;
    int colBase = blockIdx.x * 128;

    float acc[4][4][4];
    gemm_main(g_B_bf, P_GENES, rowBase, g_th_bf, P_GENES, colBase, acc, dsm, tid);

    float sk = sigmoidf_(kappa[0]);
    float sr = sigmoidf_(rho[0]);
    float Af = (1.0f - sr) * (1.0f - sk);
    float C2 = (1.0f - sr) * sk;
    float C3 = Af + sr;

    int lane = tid & 31, warp = tid >> 5;
    int wm = warp >> 2, wn = warp & 3;
    int rq = lane >> 2, kp = (lane & 3) << 1;

    float lsum = 0.0f;
    #pragma unroll
    for (int mi = 0; mi < 4; mi++) {
        #pragma unroll
        for (int nj = 0; nj < 4; nj++) {
            int r0 = rowBase + wm * 64 + mi * 16 + rq;
            int c  = colBase + wn * 32 + nj * 8 + kp;
            if (c < P_GENES) {
                #pragma unroll
                for (int half = 0; half < 2; half++) {
                    int r = r0 + half * 8;
                    if (r < P_GENES) {
                        float2 a2 = *(const float2*)(adj + (size_t)r * P_GENES + c);
                        float m0 = acc[mi][nj][half * 2 + 0];
                        float m1 = acc[mi][nj][half * 2 + 1];
                        float arg0 = (a2.x > 0.5f) ? fmaf(Af, m0, C2) : fmaf(-Af, m0, C3);
                        float arg1 = (a2.y > 0.5f) ? fmaf(Af, m1, C2) : fmaf(-Af, m1, C3);
                        if (r != c)     lsum += __logf(arg0);
                        if (r != c + 1) lsum += __logf(arg1);
                    }
                }
            }
        }
    }
    double t = block_reduce(lsum, tid);
    if (tid == 0) g_part2[blockIdx.y * gridDim.x + blockIdx.x] = t;
}

// ---------------- final reduction ----------------
__global__ void __launch_bounds__(256)
fin_kernel(float* out) {
    int tid = threadIdx.x;
    double s1 = 0.0, s2 = 0.0;
    for (int i = tid; i < NPART1; i += 256) s1 += g_part1[i];
    for (int i = tid; i < NPART2; i += 256) s2 += g_part2[i];
    #pragma unroll
    for (int off = 16; off > 0; off >>= 1) {
        s1 += __shfl_xor_sync(0xffffffff, s1, off);
        s2 += __shfl_xor_sync(0xffffffff, s2, off);
    }
    __shared__ double r1[8], r2[8];
    if ((tid & 31) == 0) { r1[tid >> 5] = s1; r2[tid >> 5] = s2; }
    __syncthreads();
    if (tid == 0) {
        double t1 = 0.0, t2 = 0.0;
        #pragma unroll
        for (int w = 0; w < 8; w++) { t1 += r1[w]; t2 += r2[w]; }
        out[0] = (float)(-(LAM_D * t1 + t2));
    }
}

// ---------------- launch ----------------
extern "C" void kernel_launch(void* const* d_in, const int* in_sizes, int n_in,
                              void* d_out, int out_size) {
    const float* X     = (const float*)d_in[0];
    const float* adj   = (const float*)d_in[1];
    // d_in[2] adj_1m, d_in[3] weights: derivable from binary adj, unused
    const float* theta = (const float*)d_in[4];
    const float* alpha = (const float*)d_in[5];
    const float* eta   = (const float*)d_in[6];
    const float* gs    = (const float*)d_in[7];
    const float* kappa = (const float*)d_in[8];
    const float* rho   = (const float*)d_in[9];
    float* out = (float*)d_out;

    const int SMEM = 2 * 128 * KS * 2;   // 61440 bytes
    cudaFuncSetAttribute(recon_kernel, cudaFuncAttributeMaxDynamicSharedMemorySize, SMEM);
    cudaFuncSetAttribute(mat_kernel,   cudaFuncAttributeMaxDynamicSharedMemorySize, SMEM);

    et_kernel<<<(L_FAC * L_FAC + 255) / 256, 256>>>(eta);
    expa_kernel<<<(N_CELLS * KP + 255) / 256, 256>>>(alpha);
    theta_kernel<<<P_GENES / 16, 256>>>(theta, gs);

    dim3 gRecon(GRID_X, GRID_Y1);
    recon_kernel<<<gRecon, 256, SMEM>>>(X);

    dim3 gMat(GRID_X, GRID_X);
    mat_kernel<<<gMat, 256, SMEM>>>(adj, kappa, rho);

    fin_kernel<<<1, 256>>>(out);
}

// round 3
// speedup vs baseline: 3.5456x; 1.5399x over previous
#include <cuda_runtime.h>
#include <cuda_bf16.h>
#include <math.h>

#define N_CELLS 10000
#define P_GENES 8000
#define L_FAC   100
#define KP      112      // padded K in global bf16 operand arrays
#define KS      120      // smem row stride in halves (bank-conflict-free)
#define LAM_D   0.01
#define DELTA_F 0.001f

#define GRID_X  63                    // ceil(8000/128)
#define GRID_Y1 79                    // ceil(10000/128)
#define NPART1  (GRID_X * GRID_Y1)    // 4977
#define NPART2  (GRID_X * GRID_X)     // 3969

// ---------------- device scratch ----------------
__device__ __align__(16) __nv_bfloat16 g_a_bf  [N_CELLS * KP];
__device__ __align__(16) __nv_bfloat16 g_thp_bf[P_GENES * KP];
__device__ __align__(16) __nv_bfloat16 g_th_bf [P_GENES * KP];
__device__ __align__(16) __nv_bfloat16 g_B_bf  [P_GENES * KP];
__device__ float  g_et[L_FAC * L_FAC];
__device__ double g_part1[5120];
__device__ double g_part2[4096];

__device__ __forceinline__ float sigmoidf_(float x) {
    return 1.0f / (1.0f + expf(-x));
}

// ---------------- et = 0.5*(sigmoid(eta)+sigmoid(eta)^T) ----------------
__global__ void et_kernel(const float* __restrict__ eta) {
    int idx = blockIdx.x * blockDim.x + threadIdx.x;
    if (idx >= L_FAC * L_FAC) return;
    int i = idx / L_FAC, j = idx % L_FAC;
    g_et[idx] = 0.5f * (sigmoidf_(eta[i * L_FAC + j]) + sigmoidf_(eta[j * L_FAC + i]));
}

// ---------------- a = exp(alpha), bf16, K-padded ----------------
__global__ void expa_kernel(const float* __restrict__ alpha) {
    int idx = blockIdx.x * blockDim.x + threadIdx.x;
    if (idx >= N_CELLS * KP) return;
    int row = idx / KP, k = idx % KP;
    float v = (k < L_FAC) ? expf(alpha[row * L_FAC + k]) : 0.0f;
    g_a_bf[idx] = __float2bfloat16(v);
}

// ---------------- per-gene: softmax, theta_, B = th@et ; 16 genes/block ----
__global__ void __launch_bounds__(256)
theta_kernel(const float* __restrict__ theta, const float* __restrict__ gs) {
    __shared__ float et_s[L_FAC * L_FAC];   // 40 KB
    __shared__ float th_s[16][L_FAC];       // 6.4 KB

    int tid = threadIdx.x;
    for (int i = tid; i < L_FAC * L_FAC; i += 256) et_s[i] = g_et[i];

    int warp = tid >> 5, lane = tid & 31;
    int rowl = warp * 2 + (lane >> 4);      // 0..15 local gene row
    int l16  = lane & 15;
    int gene = blockIdx.x * 16 + rowl;      // P divisible by 16

    float v[7];
    float mx = -1e30f;
    #pragma unroll
    for (int j = 0; j < 7; j++) {
        int idx = l16 + 16 * j;
        v[j] = (idx < L_FAC) ? theta[gene * L_FAC + idx] : -1e30f;
        mx = fmaxf(mx, v[j]);
    }
    #pragma unroll
    for (int off = 8; off > 0; off >>= 1)
        mx = fmaxf(mx, __shfl_xor_sync(0xffffffff, mx, off, 16));
    float sum = 0.0f;
    #pragma unroll
    for (int j = 0; j < 7; j++) {
        int idx = l16 + 16 * j;
        v[j] = (idx < L_FAC) ? expf(v[j] - mx) : 0.0f;
        sum += v[j];
    }
    #pragma unroll
    for (int off = 8; off > 0; off >>= 1)
        sum += __shfl_xor_sync(0xffffffff, sum, off, 16);
    float inv = 1.0f / sum;
    float gsc = sigmoidf_(gs[gene]) + DELTA_F;

    #pragma unroll
    for (int j = 0; j < 7; j++) {
        int idx = l16 + 16 * j;
        if (idx < L_FAC) {
            float th = v[j] * inv;
            th_s[rowl][idx] = th;
            g_th_bf [gene * KP + idx] = __float2bfloat16(th);
            g_thp_bf[gene * KP + idx] = __float2bfloat16(th * gsc);
        }
    }
    if (l16 < 12) {  // zero pads k=100..111
        g_th_bf [gene * KP + L_FAC + l16] = __float2bfloat16(0.0f);
        g_thp_bf[gene * KP + L_FAC + l16] = __float2bfloat16(0.0f);
        g_B_bf  [gene * KP + L_FAC + l16] = __float2bfloat16(0.0f);
    }
    __syncthreads();

    for (int idx = tid; idx < 16 * L_FAC; idx += 256) {
        int r = idx / L_FAC, c = idx % L_FAC;
        float acc = 0.0f;
        #pragma unroll 4
        for (int m = 0; m < L_FAC; m++)
            acc = fmaf(th_s[r][m], et_s[m * L_FAC + c], acc);
        g_B_bf[(blockIdx.x * 16 + r) * KP + c] = __float2bfloat16(acc);
    }
}

// =====================================================================
// bf16 mma.sync GEMM: 128x128 block tile, 512 thr (16 warps 4x4),
// warp tile 32x32, whole K panel (112) staged once in smem.
// =====================================================================
__device__ __forceinline__ void mma16816(float c[4], const unsigned a[4], const unsigned b[2]) {
    asm volatile(
        "mma.sync.aligned.m16n8k16.row.col.f32.bf16.bf16.f32 "
        "{%0,%1,%2,%3}, {%4,%5,%6,%7}, {%8,%9}, {%0,%1,%2,%3};"
        : "+f"(c[0]), "+f"(c[1]), "+f"(c[2]), "+f"(c[3])
        : "r"(a[0]), "r"(a[1]), "r"(a[2]), "r"(a[3]), "r"(b[0]), "r"(b[1]));
}

__device__ __forceinline__ void gemm_main(
    const __nv_bfloat16* __restrict__ Aglob, int Arows, int rowBase,
    const __nv_bfloat16* __restrict__ Bglob, int Brows, int colBase,
    float acc[2][4][4], char* smem, int tid)
{
    __nv_bfloat16* As = (__nv_bfloat16*)smem;
    __nv_bfloat16* Bs = As + 128 * KS;

    // stage A & B tiles: 128 rows x 14 uint4 each, padded loop of 16 cols
    #pragma unroll
    for (int i = tid; i < 128 * 16; i += 512) {
        int r = i >> 4, c = i & 15;
        if (c < 14) {
            int gr = rowBase + r;
            uint4 val = make_uint4(0u, 0u, 0u, 0u);
            if (gr < Arows) val = *(const uint4*)(Aglob + (size_t)gr * KP + c * 8);
            *(uint4*)((char*)As + r * (KS * 2) + c * 16) = val;
        }
    }
    #pragma unroll
    for (int i = tid; i < 128 * 16; i += 512) {
        int r = i >> 4, c = i & 15;
        if (c < 14) {
            int gr = colBase + r;
            uint4 val = make_uint4(0u, 0u, 0u, 0u);
            if (gr < Brows) val = *(const uint4*)(Bglob + (size_t)gr * KP + c * 8);
            *(uint4*)((char*)Bs + r * (KS * 2) + c * 16) = val;
        }
    }
    __syncthreads();

    int lane = tid & 31, warp = tid >> 5;
    int wm = warp >> 2, wn = warp & 3;
    int rq = lane >> 2;            // 0..7
    int kp = (lane & 3) << 1;      // 0,2,4,6

    #pragma unroll
    for (int mi = 0; mi < 2; mi++)
        #pragma unroll
        for (int nj = 0; nj < 4; nj++)
            #pragma unroll
            for (int q = 0; q < 4; q++) acc[mi][nj][q] = 0.0f;

    #pragma unroll
    for (int ks = 0; ks < 7; ks++) {
        int k0 = ks * 16 + kp;
        unsigned aF[2][4], bF[4][2];
        #pragma unroll
        for (int mi = 0; mi < 2; mi++) {
            const __nv_bfloat16* p = As + (wm * 32 + mi * 16 + rq) * KS + k0;
            aF[mi][0] = *(const unsigned*)(p);
            aF[mi][1] = *(const unsigned*)(p + 8 * KS);
            aF[mi][2] = *(const unsigned*)(p + 8);
            aF[mi][3] = *(const unsigned*)(p + 8 * KS + 8);
        }
        #pragma unroll
        for (int nj = 0; nj < 4; nj++) {
            const __nv_bfloat16* p = Bs + (wn * 32 + nj * 8 + rq) * KS + k0;
            bF[nj][0] = *(const unsigned*)(p);
            bF[nj][1] = *(const unsigned*)(p + 8);
        }
        #pragma unroll
        for (int mi = 0; mi < 2; mi++)
            #pragma unroll
            for (int nj = 0; nj < 4; nj++)
                mma16816(acc[mi][nj], aF[mi], bF[nj]);
    }
}

__device__ __forceinline__ double block_reduce512(float lsum, int tid) {
    __shared__ float red[16];
    #pragma unroll
    for (int off = 16; off > 0; off >>= 1)
        lsum += __shfl_xor_sync(0xffffffff, lsum, off);
    if ((tid & 31) == 0) red[tid >> 5] = lsum;
    __syncthreads();
    double t = 0.0;
    if (tid == 0) {
        #pragma unroll
        for (int w = 0; w < 16; w++) t += (double)red[w];
    }
    return t;
}

// ---- recon kernel: C = a @ thp^T, epilogue xlogy(X,C) - C ----
__global__ void __launch_bounds__(512, 2)
recon_kernel(const float* __restrict__ X) {
    extern __shared__ char dsm[];
    int tid = threadIdx.x;
    int rowBase = blockIdx.y * 128;   // cells
    int colBase = blockIdx.x * 128;   // genes

    float acc[2][4][4];
    gemm_main(g_a_bf, N_CELLS, rowBase, g_thp_bf, P_GENES, colBase, acc, dsm, tid);

    int lane = tid & 31, warp = tid >> 5;
    int wm = warp >> 2, wn = warp & 3;
    int rq = lane >> 2, kp = (lane & 3) << 1;

    float lsum = 0.0f;
    #pragma unroll
    for (int mi = 0; mi < 2; mi++) {
        #pragma unroll
        for (int nj = 0; nj < 4; nj++) {
            int r = rowBase + wm * 32 + mi * 16 + rq;
            int c = colBase + wn * 32 + nj * 8 + kp;
            if (c < P_GENES) {
                if (r < N_CELLS) {
                    float2 x = *(const float2*)(X + (size_t)r * P_GENES + c);
                    float rec = acc[mi][nj][0];
                    lsum += ((x.x > 0.0f) ? x.x * __logf(rec) : 0.0f) - rec;
                    rec = acc[mi][nj][1];
                    lsum += ((x.y > 0.0f) ? x.y * __logf(rec) : 0.0f) - rec;
                }
                if (r + 8 < N_CELLS) {
                    float2 x = *(const float2*)(X + (size_t)(r + 8) * P_GENES + c);
                    float rec = acc[mi][nj][2];
                    lsum += ((x.x > 0.0f) ? x.x * __logf(rec) : 0.0f) - rec;
                    rec = acc[mi][nj][3];
                    lsum += ((x.y > 0.0f) ? x.y * __logf(rec) : 0.0f) - rec;
                }
            }
        }
    }
    double t = block_reduce512(lsum, tid);
    if (tid == 0) g_part1[blockIdx.y * gridDim.x + blockIdx.x] = t;
}

// ---- mat kernel: M = B @ th^T, epilogue graph-prior logs ----
__global__ void __launch_bounds__(512, 2)
mat_kernel(const float* __restrict__ adj,
           const float* __restrict__ kappa,
           const float* __restrict__ rho) {
    extern __shared__ char dsm[];
    int tid = threadIdx.x;
    int rowBase = blockIdx.y * 128;
    int colBase = blockIdx.x * 128;

    float acc[2][4][4];
    gemm_main(g_B_bf, P_GENES, rowBase, g_th_bf, P_GENES, colBase, acc, dsm, tid);

    float sk = sigmoidf_(kappa[0]);
    float sr = sigmoidf_(rho[0]);
    float Af = (1.0f - sr) * (1.0f - sk);
    float C2 = (1.0f - sr) * sk;
    float C3 = Af + sr;

    int lane = tid & 31, warp = tid >> 5;
    int wm = warp >> 2, wn = warp & 3;
    int rq = lane >> 2, kp = (lane & 3) << 1;

    float lsum = 0.0f;
    #pragma unroll
    for (int mi = 0; mi < 2; mi++) {
        #pragma unroll
        for (int nj = 0; nj < 4; nj++) {
            int r0 = rowBase + wm * 32 + mi * 16 + rq;
            int c  = colBase + wn * 32 + nj * 8 + kp;
            if (c < P_GENES) {
                #pragma unroll
                for (int half = 0; half < 2; half++) {
                    int r = r0 + half * 8;
                    if (r < P_GENES) {
                        float2 a2 = *(const float2*)(adj + (size_t)r * P_GENES + c);
                        float m0 = acc[mi][nj][half * 2 + 0];
                        float m1 = acc[mi][nj][half * 2 + 1];
                        float arg0 = (a2.x > 0.5f) ? fmaf(Af, m0, C2) : fmaf(-Af, m0, C3);
                        float arg1 = (a2.y > 0.5f) ? fmaf(Af, m1, C2) : fmaf(-Af, m1, C3);
                        if (r != c)     lsum += __logf(arg0);
                        if (r != c + 1) lsum += __logf(arg1);
                    }
                }
            }
        }
    }
    double t = block_reduce512(lsum, tid);
    if (tid == 0) g_part2[blockIdx.y * gridDim.x + blockIdx.x] = t;
}

// ---------------- final reduction ----------------
__global__ void __launch_bounds__(256)
fin_kernel(float* out) {
    int tid = threadIdx.x;
    double s1 = 0.0, s2 = 0.0;
    for (int i = tid; i < NPART1; i += 256) s1 += g_part1[i];
    for (int i = tid; i < NPART2; i += 256) s2 += g_part2[i];
    #pragma unroll
    for (int off = 16; off > 0; off >>= 1) {
        s1 += __shfl_xor_sync(0xffffffff, s1, off);
        s2 += __shfl_xor_sync(0xffffffff, s2, off);
    }
    __shared__ double r1[8], r2[8];
    if ((tid & 31) == 0) { r1[tid >> 5] = s1; r2[tid >> 5] = s2; }
    __syncthreads();
    if (tid == 0) {
        double t1 = 0.0, t2 = 0.0;
        #pragma unroll
        for (int w = 0; w < 8; w++) { t1 += r1[w]; t2 += r2[w]; }
        out[0] = (float)(-(LAM_D * t1 + t2));
    }
}

// ---------------- launch ----------------
extern "C" void kernel_launch(void* const* d_in, const int* in_sizes, int n_in,
                              void* d_out, int out_size) {
    const float* X     = (const float*)d_in[0];
    const float* adj   = (const float*)d_in[1];
    // d_in[2] adj_1m, d_in[3] weights: derivable from binary adj, unused
    const float* theta = (const float*)d_in[4];
    const float* alpha = (const float*)d_in[5];
    const float* eta   = (const float*)d_in[6];
    const float* gs    = (const float*)d_in[7];
    const float* kappa = (const float*)d_in[8];
    const float* rho   = (const float*)d_in[9];
    float* out = (float*)d_out;

    const int SMEM = 2 * 128 * KS * 2;   // 61440 bytes
    cudaFuncSetAttribute(recon_kernel, cudaFuncAttributeMaxDynamicSharedMemorySize, SMEM);
    cudaFuncSetAttribute(mat_kernel,   cudaFuncAttributeMaxDynamicSharedMemorySize, SMEM);

    et_kernel<<<(L_FAC * L_FAC + 255) / 256, 256>>>(eta);
    expa_kernel<<<(N_CELLS * KP + 255) / 256, 256>>>(alpha);
    theta_kernel<<<P_GENES / 16, 256>>>(theta, gs);

    dim3 gRecon(GRID_X, GRID_Y1);
    recon_kernel<<<gRecon, 512, SMEM>>>(X);

    dim3 gMat(GRID_X, GRID_X);
    mat_kernel<<<gMat, 512, SMEM>>>(adj, kappa, rho);

    fin_kernel<<<1, 256>>>(out);
}